// round 11
// baseline (speedup 1.0000x reference)
#include <cuda_runtime.h>
#include <stdint.h>

#define CC   512
#define HWW  3136
#define WW   56
#define HH   56
#define NHEADS 16
#define DH   32
#define NB   8

// Scratch (allocation-free: static __device__ globals)
__device__ float g_q[(size_t)NB * NHEADS * HWW * DH];
__device__ float g_k[(size_t)NB * NHEADS * HWW * DH];
__device__ float g_v[(size_t)NB * NHEADS * HWW * DH];
__device__ float g_ao[(size_t)NB * HWW * CC];

// ---------------------------------------------------------------------------
// tf32 / cp.async helpers
// ---------------------------------------------------------------------------
__device__ __forceinline__ float to_tf32(float x) {
    float y;
    asm("cvt.rna.tf32.f32 %0, %1;" : "=f"(y) : "f"(x));
    return y;
}
// load smem float, round to tf32, return raw bits (frag-load path rounding —
// same rounding point as the old prep_round pass, so numerics are identical)
__device__ __forceinline__ uint32_t lds_tf32(const float* p) {
    return __float_as_uint(to_tf32(*p));
}
__device__ __forceinline__ void mma_tf32(float c[4], uint32_t a0, uint32_t a1,
                                         uint32_t a2, uint32_t a3,
                                         uint32_t b0, uint32_t b1) {
    asm volatile(
        "mma.sync.aligned.m16n8k8.row.col.f32.tf32.tf32.f32 "
        "{%0,%1,%2,%3}, {%4,%5,%6,%7}, {%8,%9}, {%0,%1,%2,%3};\n"
        : "+f"(c[0]), "+f"(c[1]), "+f"(c[2]), "+f"(c[3])
        : "r"(a0), "r"(a1), "r"(a2), "r"(a3), "r"(b0), "r"(b1));
}
__device__ __forceinline__ void cp_async16(float* smem_dst, const float* gsrc) {
    uint32_t s = (uint32_t)__cvta_generic_to_shared(smem_dst);
    asm volatile("cp.async.cg.shared.global [%0], [%1], 16;\n" :: "r"(s), "l"(gsrc));
}
#define CP_COMMIT() asm volatile("cp.async.commit_group;\n" ::: "memory")
#define CP_WAIT0()  asm volatile("cp.async.wait_group 0;\n" ::: "memory")

// Per-buffer float counts (identical for both GEMMs):
//   As = 2304 floats (qkv: [32k][72m-pad]; proj: [64m][36k-pad]), Bs = 9216.
#define SBUF 11520
#define SMEM_GEMM_BYTES (2 * SBUF * 4)   // 92160 B

// ---------------------------------------------------------------------------
// Kernel 1: fused NHWC-gather + qkv GEMM (tf32, cp.async double-buffered,
// rounding applied at frag load). BM=64, BN=256, BK=32. 8 warps, warp tile
// 64m x 32n. As: [k][m] stride 72; Bs: [n][k] stride 36. ONE sync per k-iter.
// ---------------------------------------------------------------------------
__global__ __launch_bounds__(256, 2)
void qkv_gemm_tc(const float* __restrict__ x, const float* __restrict__ w)
{
    extern __shared__ float dsm[];

    int m0 = blockIdx.x * 64;
    int n0 = blockIdx.y * 256;
    int b  = m0 / HWW;
    int pb0 = m0 % HWW;
    int t = threadIdx.x;
    int warp = t >> 5, lane = t & 31;
    int tg = lane & 3, g = lane >> 2;

    float c[4][4][4];
#pragma unroll
    for (int mt = 0; mt < 4; mt++)
#pragma unroll
        for (int nt = 0; nt < 4; nt++)
#pragma unroll
            for (int r = 0; r < 4; r++) c[mt][nt][r] = 0.f;

    const float* xb = x + (size_t)b * CC * HWW + pb0;
    int a_kk = t >> 4;            // + p*16
    int a_m4 = (t & 15) * 4;

    auto issue_tile = [&](int k0, float* buf) {
        float* As = buf;
        float* Bs = buf + 2304;
#pragma unroll
        for (int p = 0; p < 2; p++)
            cp_async16(&As[(a_kk + p * 16) * 72 + a_m4],
                       xb + (size_t)(k0 + a_kk + p * 16) * HWW + a_m4);
#pragma unroll
        for (int i = 0; i < 8; i++) {
            int idx = t + 256 * i;
            int nn = idx >> 3, k4 = (idx & 7) * 4;
            cp_async16(&Bs[nn * 36 + k4],
                       w + (size_t)(n0 + nn) * CC + k0 + k4);
        }
    };

    issue_tile(0, dsm);
    CP_COMMIT();

    for (int it = 0; it < 16; it++) {
        float* As = dsm + (it & 1) * SBUF;
        float* Bs = As + 2304;

        CP_WAIT0();
        __syncthreads();     // orders prior MMA reads before overwriting buf
        if (it < 15) {
            issue_tile((it + 1) * 32, dsm + ((it + 1) & 1) * SBUF);
            CP_COMMIT();
        }

#pragma unroll
        for (int ks = 0; ks < 4; ks++) {
            int kb = ks * 8;
            uint32_t a[4][4];
#pragma unroll
            for (int mt = 0; mt < 4; mt++) {
                int mb = mt * 16 + g;
                a[mt][0] = lds_tf32(&As[(kb + tg) * 72 + mb]);
                a[mt][1] = lds_tf32(&As[(kb + tg) * 72 + mb + 8]);
                a[mt][2] = lds_tf32(&As[(kb + tg + 4) * 72 + mb]);
                a[mt][3] = lds_tf32(&As[(kb + tg + 4) * 72 + mb + 8]);
            }
            uint32_t bq[4][2];
#pragma unroll
            for (int nt = 0; nt < 4; nt++) {
                int nn = warp * 32 + nt * 8 + g;
                bq[nt][0] = lds_tf32(&Bs[nn * 36 + kb + tg]);
                bq[nt][1] = lds_tf32(&Bs[nn * 36 + kb + tg + 4]);
            }
#pragma unroll
            for (int mt = 0; mt < 4; mt++)
#pragma unroll
                for (int nt = 0; nt < 4; nt++)
                    mma_tf32(c[mt][nt], a[mt][0], a[mt][1], a[mt][2], a[mt][3],
                             bq[nt][0], bq[nt][1]);
        }
        // no bottom sync: next iter's top sync provides the ordering
    }

    // ---- epilogue: warp covers exactly 32 n = one (sel, head) ----
    int nwb  = n0 + warp * 32;
    int sel  = nwb >> 9;
    int head = (nwb & 511) >> 5;
    float scl = (sel == 0) ? 0.17677669529663687f : 1.0f;
    float* dst = (sel == 0) ? g_q : (sel == 1) ? g_k : g_v;
    size_t plane = ((size_t)b * NHEADS + head) * HWW;
#pragma unroll
    for (int mt = 0; mt < 4; mt++) {
#pragma unroll
        for (int h = 0; h < 2; h++) {
            int hw = pb0 + mt * 16 + g + h * 8;
            float* row = dst + (plane + hw) * DH;
#pragma unroll
            for (int nt = 0; nt < 4; nt++) {
                int dd = nt * 8 + 2 * tg;
                float2 v2 = make_float2(c[mt][nt][h * 2] * scl,
                                        c[mt][nt][h * 2 + 1] * scl);
                *(float2*)(row + dd) = v2;
            }
        }
    }
}

// ---------------------------------------------------------------------------
// Kernel 2: neighborhood attention, two-phase, vectorized QK. Unchanged
// except g_ao is stored in full fp32 (proj rounds its A-frags itself).
// ---------------------------------------------------------------------------
__global__ __launch_bounds__(256)
void attn_kernel(const float* __restrict__ rpb)
{
    __shared__ __align__(16) float ks[140 * 36];
    __shared__ __align__(16) float vs[140 * 33];
    __shared__ __align__(16) float pw[32 * 52];
    __shared__ __align__(16) float rs[169];

    int bh   = blockIdx.z;
    int head = bh & (NHEADS - 1);
    int bb   = bh >> 4;
    int i0   = blockIdx.y * 4;
    int j0   = blockIdx.x * 8;
    int rstart = max(0, min(i0 - 3, HH - 10));
    int cstart = max(0, min(j0 - 3, WW - 14));

    const float* kp = g_k + (size_t)bh * HWW * DH;
    const float* vp = g_v + (size_t)bh * HWW * DH;
    const float* qp = g_q + (size_t)bh * HWW * DH;

    for (int idx = threadIdx.x; idx < 140 * 32; idx += 256) {
        int r = idx >> 5, d = idx & 31;
        int hr = r / 14, hc = r - hr * 14;
        size_t gofs = ((size_t)(rstart + hr) * WW + cstart + hc) * DH + d;
        ks[r * 36 + d] = kp[gofs];
        vs[r * 33 + d] = vp[gofs];
    }
    for (int idx = threadIdx.x; idx < 32 * 32; idx += 256) {
        int p = idx >> 5, d = idx & 31;
        int qi = i0 + (p >> 3), qj = j0 + (p & 7);
        pw[p * 52 + d] = qp[((size_t)qi * WW + qj) * DH + d];
    }
    if (threadIdx.x < 169) rs[threadIdx.x] = rpb[head * 169 + threadIdx.x];
    __syncthreads();

    int warp = threadIdx.x >> 5, lane = threadIdx.x & 31;
    int i  = i0 + (warp >> 1);
    int si = min(max(i - 3, 0), HH - 7);

    int a0 = lane / 7, c0 = lane - a0 * 7;
    int n1 = lane + 32;
    int a1 = n1 / 7, c1 = n1 - a1 * 7;
    bool l2 = lane < 17;
    if (!l2) { a1 = 0; c1 = 0; }
    int rofs0 = a0 * 14 + c0;
    int rofs1 = a1 * 14 + c1;

    for (int cc = 0; cc < 4; cc++) {
        int j  = j0 + (warp & 1) * 4 + cc;
        int sj = min(max(j - 3, 0), WW - 7);
        int pix = (warp >> 1) * 8 + (warp & 1) * 4 + cc;
        int nbase = (si - rstart) * 14 + (sj - cstart);

        const float* q   = &pw[pix * 52];
        const float* k0p = &ks[(nbase + rofs0) * 36];
        const float* k1p = &ks[(nbase + rofs1) * 36];
        float dot0 = 0.f, dot1 = 0.f;
#pragma unroll
        for (int d4 = 0; d4 < 8; d4++) {
            float4 qv  = *(const float4*)(q   + d4 * 4);
            float4 k0v = *(const float4*)(k0p + d4 * 4);
            float4 k1v = *(const float4*)(k1p + d4 * 4);
            dot0 = fmaf(qv.x, k0v.x, dot0);
            dot1 = fmaf(qv.x, k1v.x, dot1);
            dot0 = fmaf(qv.y, k0v.y, dot0);
            dot1 = fmaf(qv.y, k1v.y, dot1);
            dot0 = fmaf(qv.z, k0v.z, dot0);
            dot1 = fmaf(qv.z, k1v.z, dot1);
            dot0 = fmaf(qv.w, k0v.w, dot0);
            dot1 = fmaf(qv.w, k1v.w, dot1);
        }
        int bi = (si - i + 6) * 13 + (sj - j + 6);
        float lg0 = dot0 + rs[bi + a0 * 13 + c0];
        float lg1 = l2 ? (dot1 + rs[bi + a1 * 13 + c1]) : -1e30f;

        float m = fmaxf(lg0, lg1);
#pragma unroll
        for (int s = 16; s > 0; s >>= 1)
            m = fmaxf(m, __shfl_xor_sync(0xffffffffu, m, s));
        float e0 = __expf(lg0 - m);
        float e1 = l2 ? __expf(lg1 - m) : 0.f;
        float sum = e0 + e1;
#pragma unroll
        for (int s = 16; s > 0; s >>= 1)
            sum += __shfl_xor_sync(0xffffffffu, sum, s);
        float inv = 1.0f / sum;

        float* wslot = &pw[pix * 52];
        wslot[lane] = e0;
        if (l2) wslot[32 + lane] = e1;
        __syncwarp();

        float acc = 0.f;
#pragma unroll
        for (int a = 0; a < 7; a++) {
            const float* vrow = &vs[((si + a - rstart) * 14 + (sj - cstart)) * 33 + lane];
#pragma unroll
            for (int c = 0; c < 7; c++)
                acc = fmaf(wslot[a * 7 + c], vrow[c * 33], acc);
        }
        __syncwarp();

        size_t pg = (size_t)bb * HWW + (size_t)i * WW + j;
        g_ao[pg * CC + head * DH + lane] = acc * inv;
    }
}

// ---------------------------------------------------------------------------
// Kernel 3: proj GEMM (tf32, cp.async double-buffered, frag-load rounding)
// + bias + NCHW store. BM=64, BN=256, BK=32, warp tile 64x32.
// As: [m][k] stride 36; Bs: [n][k] stride 36. ONE sync per k-iter.
// ---------------------------------------------------------------------------
__global__ __launch_bounds__(256, 2)
void proj_gemm_tc(const float* __restrict__ w, const float* __restrict__ bias,
                  float* __restrict__ y)
{
    extern __shared__ float dsm[];

    int m0 = blockIdx.x * 64;
    int n0 = blockIdx.y * 256;
    int b  = m0 / HWW;
    int pb0 = m0 % HWW;
    int t = threadIdx.x;
    int warp = t >> 5, lane = t & 31;
    int tg = lane & 3, g = lane >> 2;

    float c[4][4][4];
#pragma unroll
    for (int mt = 0; mt < 4; mt++)
#pragma unroll
        for (int nt = 0; nt < 4; nt++)
#pragma unroll
            for (int r = 0; r < 4; r++) c[mt][nt][r] = 0.f;

    const float* A = g_ao + (size_t)m0 * CC;   // device-side symbol ref

    auto issue_tile = [&](int k0, float* buf) {
        float* As = buf;
        float* Bs = buf + 2304;
#pragma unroll
        for (int p = 0; p < 2; p++) {
            int idx = t + 256 * p;
            int mm = idx >> 3, k4 = (idx & 7) * 4;
            cp_async16(&As[mm * 36 + k4], A + (size_t)mm * CC + k0 + k4);
        }
#pragma unroll
        for (int i = 0; i < 8; i++) {
            int idx = t + 256 * i;
            int nn = idx >> 3, k4 = (idx & 7) * 4;
            cp_async16(&Bs[nn * 36 + k4], w + (size_t)(n0 + nn) * CC + k0 + k4);
        }
    };

    issue_tile(0, dsm);
    CP_COMMIT();

    for (int it = 0; it < 16; it++) {
        float* As = dsm + (it & 1) * SBUF;
        float* Bs = As + 2304;

        CP_WAIT0();
        __syncthreads();
        if (it < 15) {
            issue_tile((it + 1) * 32, dsm + ((it + 1) & 1) * SBUF);
            CP_COMMIT();
        }

#pragma unroll
        for (int ks = 0; ks < 4; ks++) {
            int kb = ks * 8;
            uint32_t a[4][4];
#pragma unroll
            for (int mt = 0; mt < 4; mt++) {
                int mb = mt * 16 + g;
                a[mt][0] = lds_tf32(&As[mb * 36 + kb + tg]);
                a[mt][1] = lds_tf32(&As[(mb + 8) * 36 + kb + tg]);
                a[mt][2] = lds_tf32(&As[mb * 36 + kb + tg + 4]);
                a[mt][3] = lds_tf32(&As[(mb + 8) * 36 + kb + tg + 4]);
            }
            uint32_t bq[4][2];
#pragma unroll
            for (int nt = 0; nt < 4; nt++) {
                int nn = warp * 32 + nt * 8 + g;
                bq[nt][0] = lds_tf32(&Bs[nn * 36 + kb + tg]);
                bq[nt][1] = lds_tf32(&Bs[nn * 36 + kb + tg + 4]);
            }
#pragma unroll
            for (int mt = 0; mt < 4; mt++)
#pragma unroll
                for (int nt = 0; nt < 4; nt++)
                    mma_tf32(c[mt][nt], a[mt][0], a[mt][1], a[mt][2], a[mt][3],
                             bq[nt][0], bq[nt][1]);
        }
        // no bottom sync
    }

    // ---- epilogue: NCHW store with bias ----
#pragma unroll
    for (int nt = 0; nt < 4; nt++) {
        int n = n0 + warp * 32 + nt * 8 + 2 * tg;
        float bv0 = bias[n];
        float bv1 = bias[n + 1];
        float* y0 = y + ((size_t)b * CC + n) * HWW;
        float* y1 = y0 + HWW;
#pragma unroll
        for (int mt = 0; mt < 4; mt++) {
#pragma unroll
            for (int h = 0; h < 2; h++) {
                int hw = pb0 + mt * 16 + g + h * 8;
                y0[hw] = c[mt][nt][h * 2]     + bv0;
                y1[hw] = c[mt][nt][h * 2 + 1] + bv1;
            }
        }
    }
}

// ---------------------------------------------------------------------------
extern "C" void kernel_launch(void* const* d_in, const int* in_sizes, int n_in,
                              void* d_out, int out_size)
{
    const float* x      = (const float*)d_in[0];
    const float* qkv_w  = (const float*)d_in[1];
    const float* rpb    = (const float*)d_in[2];
    const float* proj_w = (const float*)d_in[3];
    const float* proj_b = (const float*)d_in[4];
    float* y = (float*)d_out;

    cudaFuncSetAttribute(qkv_gemm_tc,
        cudaFuncAttributeMaxDynamicSharedMemorySize, SMEM_GEMM_BYTES);
    cudaFuncSetAttribute(proj_gemm_tc,
        cudaFuncAttributeMaxDynamicSharedMemorySize, SMEM_GEMM_BYTES);

    qkv_gemm_tc<<<dim3(392, 6), 256, SMEM_GEMM_BYTES>>>(x, qkv_w);
    attn_kernel<<<dim3(7, 14, NB * NHEADS), 256>>>(rpb);
    proj_gemm_tc<<<dim3(392, 2), 256, SMEM_GEMM_BYTES>>>(proj_w, proj_b, y);
}

// round 12
// speedup vs baseline: 1.0474x; 1.0474x over previous
#include <cuda_runtime.h>
#include <stdint.h>

#define CC   512
#define HWW  3136
#define WW   56
#define HH   56
#define NHEADS 16
#define DH   32
#define NB   8

// Scratch (allocation-free: static __device__ globals)
__device__ float g_q[(size_t)NB * NHEADS * HWW * DH];
__device__ float g_k[(size_t)NB * NHEADS * HWW * DH];
__device__ float g_v[(size_t)NB * NHEADS * HWW * DH];
__device__ float g_ao[(size_t)NB * HWW * CC];

// ---------------------------------------------------------------------------
// tf32 / cp.async helpers
// ---------------------------------------------------------------------------
__device__ __forceinline__ float to_tf32(float x) {
    float y;
    asm("cvt.rna.tf32.f32 %0, %1;" : "=f"(y) : "f"(x));
    return y;
}
__device__ __forceinline__ uint32_t lds_tf32(const float* p) {
    return __float_as_uint(to_tf32(*p));
}
__device__ __forceinline__ void mma_tf32(float c[4], uint32_t a0, uint32_t a1,
                                         uint32_t a2, uint32_t a3,
                                         uint32_t b0, uint32_t b1) {
    asm volatile(
        "mma.sync.aligned.m16n8k8.row.col.f32.tf32.tf32.f32 "
        "{%0,%1,%2,%3}, {%4,%5,%6,%7}, {%8,%9}, {%0,%1,%2,%3};\n"
        : "+f"(c[0]), "+f"(c[1]), "+f"(c[2]), "+f"(c[3])
        : "r"(a0), "r"(a1), "r"(a2), "r"(a3), "r"(b0), "r"(b1));
}
__device__ __forceinline__ void cp_async16(float* smem_dst, const float* gsrc) {
    uint32_t s = (uint32_t)__cvta_generic_to_shared(smem_dst);
    asm volatile("cp.async.cg.shared.global [%0], [%1], 16;\n" :: "r"(s), "l"(gsrc));
}
#define CP_COMMIT() asm volatile("cp.async.commit_group;\n" ::: "memory")
#define CP_WAIT0()  asm volatile("cp.async.wait_group 0;\n" ::: "memory")

#define SBUF 11520
#define SMEM_GEMM_BYTES (2 * SBUF * 4)   // 92160 B

// Attention dynamic-smem layout (floats):
//   ks: [0, 7056)          196 halo rows * 36
//   vs: [7056, 14112)      196 halo rows * 36
//   pw: [14112, 17440)     64 pixels * 52 (q staging, then weights)
//   rs: [17440, 17616)     169 (+pad)
#define ATT_KS 0
#define ATT_VS 7056
#define ATT_PW 14112
#define ATT_RS 17440
#define SMEM_ATTN_BYTES ((17440 + 176) * 4)   // 70464 B

// ---------------------------------------------------------------------------
// Kernel 1: fused NHWC-gather + qkv GEMM (tf32, cp.async double-buffered,
// rounding applied at frag load). BM=64, BN=256, BK=32. UNCHANGED from R11.
// ---------------------------------------------------------------------------
__global__ __launch_bounds__(256, 2)
void qkv_gemm_tc(const float* __restrict__ x, const float* __restrict__ w)
{
    extern __shared__ float dsm[];

    int m0 = blockIdx.x * 64;
    int n0 = blockIdx.y * 256;
    int b  = m0 / HWW;
    int pb0 = m0 % HWW;
    int t = threadIdx.x;
    int warp = t >> 5, lane = t & 31;
    int tg = lane & 3, g = lane >> 2;

    float c[4][4][4];
#pragma unroll
    for (int mt = 0; mt < 4; mt++)
#pragma unroll
        for (int nt = 0; nt < 4; nt++)
#pragma unroll
            for (int r = 0; r < 4; r++) c[mt][nt][r] = 0.f;

    const float* xb = x + (size_t)b * CC * HWW + pb0;
    int a_kk = t >> 4;
    int a_m4 = (t & 15) * 4;

    auto issue_tile = [&](int k0, float* buf) {
        float* As = buf;
        float* Bs = buf + 2304;
#pragma unroll
        for (int p = 0; p < 2; p++)
            cp_async16(&As[(a_kk + p * 16) * 72 + a_m4],
                       xb + (size_t)(k0 + a_kk + p * 16) * HWW + a_m4);
#pragma unroll
        for (int i = 0; i < 8; i++) {
            int idx = t + 256 * i;
            int nn = idx >> 3, k4 = (idx & 7) * 4;
            cp_async16(&Bs[nn * 36 + k4],
                       w + (size_t)(n0 + nn) * CC + k0 + k4);
        }
    };

    issue_tile(0, dsm);
    CP_COMMIT();

    for (int it = 0; it < 16; it++) {
        float* As = dsm + (it & 1) * SBUF;
        float* Bs = As + 2304;

        CP_WAIT0();
        __syncthreads();
        if (it < 15) {
            issue_tile((it + 1) * 32, dsm + ((it + 1) & 1) * SBUF);
            CP_COMMIT();
        }

#pragma unroll
        for (int ks = 0; ks < 4; ks++) {
            int kb = ks * 8;
            uint32_t a[4][4];
#pragma unroll
            for (int mt = 0; mt < 4; mt++) {
                int mb = mt * 16 + g;
                a[mt][0] = lds_tf32(&As[(kb + tg) * 72 + mb]);
                a[mt][1] = lds_tf32(&As[(kb + tg) * 72 + mb + 8]);
                a[mt][2] = lds_tf32(&As[(kb + tg + 4) * 72 + mb]);
                a[mt][3] = lds_tf32(&As[(kb + tg + 4) * 72 + mb + 8]);
            }
            uint32_t bq[4][2];
#pragma unroll
            for (int nt = 0; nt < 4; nt++) {
                int nn = warp * 32 + nt * 8 + g;
                bq[nt][0] = lds_tf32(&Bs[nn * 36 + kb + tg]);
                bq[nt][1] = lds_tf32(&Bs[nn * 36 + kb + tg + 4]);
            }
#pragma unroll
            for (int mt = 0; mt < 4; mt++)
#pragma unroll
                for (int nt = 0; nt < 4; nt++)
                    mma_tf32(c[mt][nt], a[mt][0], a[mt][1], a[mt][2], a[mt][3],
                             bq[nt][0], bq[nt][1]);
        }
    }

    int nwb  = n0 + warp * 32;
    int sel  = nwb >> 9;
    int head = (nwb & 511) >> 5;
    float scl = (sel == 0) ? 0.17677669529663687f : 1.0f;
    float* dst = (sel == 0) ? g_q : (sel == 1) ? g_k : g_v;
    size_t plane = ((size_t)b * NHEADS + head) * HWW;
#pragma unroll
    for (int mt = 0; mt < 4; mt++) {
#pragma unroll
        for (int h = 0; h < 2; h++) {
            int hw = pb0 + mt * 16 + g + h * 8;
            float* row = dst + (plane + hw) * DH;
#pragma unroll
            for (int nt = 0; nt < 4; nt++) {
                int dd = nt * 8 + 2 * tg;
                float2 v2 = make_float2(c[mt][nt][h * 2] * scl,
                                        c[mt][nt][h * 2 + 1] * scl);
                *(float2*)(row + dd) = v2;
            }
        }
    }
}

// ---------------------------------------------------------------------------
// Kernel 2: neighborhood attention, REWRITTEN.
//   Tile 8x8 pixels/block (halo 14x14, redundancy 3.06x vs 4.4x), warp = row.
//   float4 halo + q staging; ks/vs both stride-36 rows.
//   QK dots: 2 partial accumulators; AV: 4 partial accumulators.
// ---------------------------------------------------------------------------
__global__ __launch_bounds__(256, 3)
void attn_kernel(const float* __restrict__ rpb)
{
    extern __shared__ float asm_[];
    float* ks = asm_ + ATT_KS;
    float* vs = asm_ + ATT_VS;
    float* pw = asm_ + ATT_PW;
    float* rs = asm_ + ATT_RS;

    int bh   = blockIdx.z;
    int head = bh & (NHEADS - 1);
    int bb   = bh >> 4;
    int i0   = blockIdx.y * 8;
    int j0   = blockIdx.x * 8;
    int rstart = max(0, min(i0 - 3, HH - 14));
    int cstart = max(0, min(j0 - 3, WW - 14));

    const float* kp = g_k + (size_t)bh * HWW * DH;
    const float* vp = g_v + (size_t)bh * HWW * DH;
    const float* qp = g_q + (size_t)bh * HWW * DH;

    int tid = threadIdx.x;

    // halo: 196 rows x 32 d, float4 (8 chunks per row)
    for (int idx = tid; idx < 196 * 8; idx += 256) {
        int r = idx >> 3, d4 = (idx & 7) << 2;
        int hr = r / 14, hc = r - hr * 14;
        size_t gofs = ((size_t)(rstart + hr) * WW + cstart + hc) * DH + d4;
        *(float4*)&ks[r * 36 + d4] = *(const float4*)(kp + gofs);
        *(float4*)&vs[r * 36 + d4] = *(const float4*)(vp + gofs);
    }
    // q staging: 64 pixels x 32 d, float4
    for (int idx = tid; idx < 64 * 8; idx += 256) {
        int p = idx >> 3, d4 = (idx & 7) << 2;
        int qi = i0 + (p >> 3), qj = j0 + (p & 7);
        *(float4*)&pw[p * 52 + d4] =
            *(const float4*)(qp + ((size_t)qi * WW + qj) * DH + d4);
    }
    if (tid < 169) rs[tid] = rpb[head * 169 + tid];
    __syncthreads();

    int warp = tid >> 5, lane = tid & 31;
    int i  = i0 + warp;
    int si = min(max(i - 3, 0), HH - 7);

    // per-lane neighbor decomposition (fixed across pixels)
    int a0 = lane / 7, c0 = lane - a0 * 7;
    int n1 = lane + 32;
    int a1 = n1 / 7, c1 = n1 - a1 * 7;
    bool l2 = lane < 17;
    if (!l2) { a1 = 0; c1 = 0; }
    int rofs0 = a0 * 14 + c0;
    int rofs1 = a1 * 14 + c1;

    for (int jj = 0; jj < 8; jj++) {
        int j  = j0 + jj;
        int sj = min(max(j - 3, 0), WW - 7);
        int pix = warp * 8 + jj;
        int nbase = (si - rstart) * 14 + (sj - cstart);

        const float* q   = &pw[pix * 52];
        const float* k0p = &ks[(nbase + rofs0) * 36];
        const float* k1p = &ks[(nbase + rofs1) * 36];
        float d0a = 0.f, d0b = 0.f, d1a = 0.f, d1b = 0.f;
#pragma unroll
        for (int d4 = 0; d4 < 8; d4++) {
            float4 qv  = *(const float4*)(q   + d4 * 4);
            float4 k0v = *(const float4*)(k0p + d4 * 4);
            float4 k1v = *(const float4*)(k1p + d4 * 4);
            d0a = fmaf(qv.x, k0v.x, d0a);
            d0b = fmaf(qv.y, k0v.y, d0b);
            d1a = fmaf(qv.x, k1v.x, d1a);
            d1b = fmaf(qv.y, k1v.y, d1b);
            d0a = fmaf(qv.z, k0v.z, d0a);
            d0b = fmaf(qv.w, k0v.w, d0b);
            d1a = fmaf(qv.z, k1v.z, d1a);
            d1b = fmaf(qv.w, k1v.w, d1b);
        }
        int bi = (si - i + 6) * 13 + (sj - j + 6);
        float lg0 = (d0a + d0b) + rs[bi + a0 * 13 + c0];
        float lg1 = l2 ? ((d1a + d1b) + rs[bi + a1 * 13 + c1]) : -1e30f;

        // softmax across 49 neighbors spread over lanes
        float m = fmaxf(lg0, lg1);
#pragma unroll
        for (int s = 16; s > 0; s >>= 1)
            m = fmaxf(m, __shfl_xor_sync(0xffffffffu, m, s));
        float e0 = __expf(lg0 - m);
        float e1 = l2 ? __expf(lg1 - m) : 0.f;
        float sum = e0 + e1;
#pragma unroll
        for (int s = 16; s > 0; s >>= 1)
            sum += __shfl_xor_sync(0xffffffffu, sum, s);
        float inv = 1.0f / sum;

        // stage unnormalized weights into the (now dead) q slot
        float* wslot = &pw[pix * 52];
        wslot[lane] = e0;
        if (l2) wslot[32 + lane] = e1;
        __syncwarp();

        // AV phase: lane = dim, 4 interleaved partial accumulators
        float ac0 = 0.f, ac1 = 0.f, ac2 = 0.f, ac3 = 0.f;
#pragma unroll
        for (int a = 0; a < 7; a++) {
            const float* vrow = &vs[((si + a - rstart) * 14 + (sj - cstart)) * 36 + lane];
            const float* wr = wslot + a * 7;
            ac0 = fmaf(wr[0], vrow[0],       ac0);
            ac1 = fmaf(wr[1], vrow[36],      ac1);
            ac2 = fmaf(wr[2], vrow[72],      ac2);
            ac3 = fmaf(wr[3], vrow[108],     ac3);
            ac0 = fmaf(wr[4], vrow[144],     ac0);
            ac1 = fmaf(wr[5], vrow[180],     ac1);
            ac2 = fmaf(wr[6], vrow[216],     ac2);
        }
        float acc = (ac0 + ac1) + (ac2 + ac3);
        __syncwarp();   // protect wslot until all lanes consumed it

        size_t pg = (size_t)bb * HWW + (size_t)i * WW + j;
        g_ao[pg * CC + head * DH + lane] = acc * inv;
    }
}

// ---------------------------------------------------------------------------
// Kernel 3: proj GEMM (tf32, cp.async double-buffered, frag-load rounding)
// + bias + NCHW store. UNCHANGED from R11.
// ---------------------------------------------------------------------------
__global__ __launch_bounds__(256, 2)
void proj_gemm_tc(const float* __restrict__ w, const float* __restrict__ bias,
                  float* __restrict__ y)
{
    extern __shared__ float dsm[];

    int m0 = blockIdx.x * 64;
    int n0 = blockIdx.y * 256;
    int b  = m0 / HWW;
    int pb0 = m0 % HWW;
    int t = threadIdx.x;
    int warp = t >> 5, lane = t & 31;
    int tg = lane & 3, g = lane >> 2;

    float c[4][4][4];
#pragma unroll
    for (int mt = 0; mt < 4; mt++)
#pragma unroll
        for (int nt = 0; nt < 4; nt++)
#pragma unroll
            for (int r = 0; r < 4; r++) c[mt][nt][r] = 0.f;

    const float* A = g_ao + (size_t)m0 * CC;

    auto issue_tile = [&](int k0, float* buf) {
        float* As = buf;
        float* Bs = buf + 2304;
#pragma unroll
        for (int p = 0; p < 2; p++) {
            int idx = t + 256 * p;
            int mm = idx >> 3, k4 = (idx & 7) * 4;
            cp_async16(&As[mm * 36 + k4], A + (size_t)mm * CC + k0 + k4);
        }
#pragma unroll
        for (int i = 0; i < 8; i++) {
            int idx = t + 256 * i;
            int nn = idx >> 3, k4 = (idx & 7) * 4;
            cp_async16(&Bs[nn * 36 + k4], w + (size_t)(n0 + nn) * CC + k0 + k4);
        }
    };

    issue_tile(0, dsm);
    CP_COMMIT();

    for (int it = 0; it < 16; it++) {
        float* As = dsm + (it & 1) * SBUF;
        float* Bs = As + 2304;

        CP_WAIT0();
        __syncthreads();
        if (it < 15) {
            issue_tile((it + 1) * 32, dsm + ((it + 1) & 1) * SBUF);
            CP_COMMIT();
        }

#pragma unroll
        for (int ks = 0; ks < 4; ks++) {
            int kb = ks * 8;
            uint32_t a[4][4];
#pragma unroll
            for (int mt = 0; mt < 4; mt++) {
                int mb = mt * 16 + g;
                a[mt][0] = lds_tf32(&As[mb * 36 + kb + tg]);
                a[mt][1] = lds_tf32(&As[(mb + 8) * 36 + kb + tg]);
                a[mt][2] = lds_tf32(&As[mb * 36 + kb + tg + 4]);
                a[mt][3] = lds_tf32(&As[(mb + 8) * 36 + kb + tg + 4]);
            }
            uint32_t bq[4][2];
#pragma unroll
            for (int nt = 0; nt < 4; nt++) {
                int nn = warp * 32 + nt * 8 + g;
                bq[nt][0] = lds_tf32(&Bs[nn * 36 + kb + tg]);
                bq[nt][1] = lds_tf32(&Bs[nn * 36 + kb + tg + 4]);
            }
#pragma unroll
            for (int mt = 0; mt < 4; mt++)
#pragma unroll
                for (int nt = 0; nt < 4; nt++)
                    mma_tf32(c[mt][nt], a[mt][0], a[mt][1], a[mt][2], a[mt][3],
                             bq[nt][0], bq[nt][1]);
        }
    }

#pragma unroll
    for (int nt = 0; nt < 4; nt++) {
        int n = n0 + warp * 32 + nt * 8 + 2 * tg;
        float bv0 = bias[n];
        float bv1 = bias[n + 1];
        float* y0 = y + ((size_t)b * CC + n) * HWW;
        float* y1 = y0 + HWW;
#pragma unroll
        for (int mt = 0; mt < 4; mt++) {
#pragma unroll
            for (int h = 0; h < 2; h++) {
                int hw = pb0 + mt * 16 + g + h * 8;
                y0[hw] = c[mt][nt][h * 2]     + bv0;
                y1[hw] = c[mt][nt][h * 2 + 1] + bv1;
            }
        }
    }
}

// ---------------------------------------------------------------------------
extern "C" void kernel_launch(void* const* d_in, const int* in_sizes, int n_in,
                              void* d_out, int out_size)
{
    const float* x      = (const float*)d_in[0];
    const float* qkv_w  = (const float*)d_in[1];
    const float* rpb    = (const float*)d_in[2];
    const float* proj_w = (const float*)d_in[3];
    const float* proj_b = (const float*)d_in[4];
    float* y = (float*)d_out;

    cudaFuncSetAttribute(qkv_gemm_tc,
        cudaFuncAttributeMaxDynamicSharedMemorySize, SMEM_GEMM_BYTES);
    cudaFuncSetAttribute(proj_gemm_tc,
        cudaFuncAttributeMaxDynamicSharedMemorySize, SMEM_GEMM_BYTES);
    cudaFuncSetAttribute(attn_kernel,
        cudaFuncAttributeMaxDynamicSharedMemorySize, SMEM_ATTN_BYTES);

    qkv_gemm_tc<<<dim3(392, 6), 256, SMEM_GEMM_BYTES>>>(x, qkv_w);
    attn_kernel<<<dim3(7, 7, NB * NHEADS), 256, SMEM_ATTN_BYTES>>>(rpb);
    proj_gemm_tc<<<dim3(392, 2), 256, SMEM_GEMM_BYTES>>>(proj_w, proj_b, y);
}